// round 15
// baseline (speedup 1.0000x reference)
#include <cuda_runtime.h>
#include <math.h>

// Problem dims (fixed by reference)
#define B   128
#define N   2048
#define H   768
#define H2  1536
#define S   8           // N-splits for pooling (1024 blocks = one resident wave)
#define NPS (N / S)     // 256 rows per split
#define KS  3           // k-splits for gemm
#define KPS (H / KS)    // 256 k per split
#define NBLK (S * B)    // 1024 pool blocks (all resident: 148*7=1036)
#define LN_EPS 1e-5f

// Scratch (static device globals; no allocation allowed)
__device__ float g_partial[B * S * H];     // 3.1 MB
__device__ float g_pooled[B * H];          // 393 KB
__device__ float g_hp[KS * B * H2];        // 2.4 MB gemm k-split partials

// grid-barrier state (epoch-based; persists across graph replays)
__device__ unsigned g_bar_count = 0u;
__device__ unsigned g_bar_gen   = 0u;

// ---- packed f32x2 helpers (FFMA2: PTX-only, 2x fp32 FMA throughput) ----
__device__ __forceinline__ unsigned long long pack2(float lo, float hi) {
    unsigned long long r;
    asm("mov.b64 %0, {%1, %2};" : "=l"(r) : "f"(lo), "f"(hi));
    return r;
}
__device__ __forceinline__ unsigned long long fma2(
    unsigned long long a, unsigned long long b, unsigned long long c) {
    unsigned long long d;
    asm("fma.rn.f32x2 %0, %1, %2, %3;" : "=l"(d) : "l"(a), "l"(b), "l"(c));
    return d;
}
__device__ __forceinline__ void unpack2(unsigned long long v, float& lo, float& hi) {
    asm("mov.b64 {%0, %1}, %2;" : "=f"(lo), "=f"(hi) : "l"(v));
}

// ---------------------------------------------------------------------------
// Kernel 1: fused mean-pool (partial + fold). grid = (S=8, B) = 1024 blocks,
// 192 threads, __launch_bounds__(192,7) -> all resident.
// Proven R8: 118.9us, 85% of HBM spec. DO NOT TOUCH.
// ---------------------------------------------------------------------------
__global__ void __launch_bounds__(192, 7) pool_fused(const float* __restrict__ v) {
    const int s = blockIdx.x;
    const int b = blockIdx.y;
    const int t = threadIdx.x;              // 0..191, 192*4 = 768 = H

    unsigned base_gen = 0;
    if (t == 0) base_gen = *(volatile unsigned*)&g_bar_gen;

    const float4* p = reinterpret_cast<const float4*>(
        v + ((size_t)b * N + (size_t)s * NPS) * H) + t;
    const int stride = H / 4;

    float4 a0 = make_float4(0.f,0.f,0.f,0.f), a1 = a0, a2 = a0, a3 = a0;
    #pragma unroll 1
    for (int n = 0; n < NPS; n += 4) {
        float4 x0 = __ldcs(p + (n + 0) * stride);
        float4 x1 = __ldcs(p + (n + 1) * stride);
        float4 x2 = __ldcs(p + (n + 2) * stride);
        float4 x3 = __ldcs(p + (n + 3) * stride);
        a0.x += x0.x; a0.y += x0.y; a0.z += x0.z; a0.w += x0.w;
        a1.x += x1.x; a1.y += x1.y; a1.z += x1.z; a1.w += x1.w;
        a2.x += x2.x; a2.y += x2.y; a2.z += x2.z; a2.w += x2.w;
        a3.x += x3.x; a3.y += x3.y; a3.z += x3.z; a3.w += x3.w;
    }
    float4 acc;
    acc.x = (a0.x + a1.x) + (a2.x + a3.x);
    acc.y = (a0.y + a1.y) + (a2.y + a3.y);
    acc.z = (a0.z + a1.z) + (a2.z + a3.z);
    acc.w = (a0.w + a1.w) + (a2.w + a3.w);
    *(reinterpret_cast<float4*>(g_partial + ((size_t)b * S + s) * H) + t) = acc;

    // grid barrier (all 1024 blocks resident by construction)
    __syncthreads();
    if (t == 0) {
        const unsigned target = base_gen + 1u;
        __threadfence();
        if (atomicAdd(&g_bar_count, 1u) == (unsigned)(NBLK - 1)) {
            g_bar_count = 0u;
            __threadfence();
            *(volatile unsigned*)&g_bar_gen = target;
        } else if (s == 0) {
            while ((int)(*(volatile unsigned*)&g_bar_gen - target) < 0)
                __nanosleep(64);
        }
        __threadfence();
    }
    __syncthreads();

    // fold S partials, scale by 1/N (128 blocks participate)
    if (s == 0) {
        float4 r = make_float4(0.f, 0.f, 0.f, 0.f);
        #pragma unroll
        for (int ss = 0; ss < S; ss++) {
            float4 x = *(reinterpret_cast<const float4*>(
                g_partial + ((size_t)b * S + ss) * H) + t);
            r.x += x.x; r.y += x.y; r.z += x.z; r.w += x.w;
        }
        const float inv = 1.0f / (float)N;
        r.x *= inv; r.y *= inv; r.z *= inv; r.w *= inv;
        *(reinterpret_cast<float4*>(g_pooled + (size_t)b * H) + t) = r;
    }
}

// ---------------------------------------------------------------------------
// Kernel 2: k-split GEMM partials with packed FFMA2 inner loop.
// grid = (24 f-tiles, 2 b-tiles, 3 k-splits) = 144 blocks, 256 threads.
// Thread tile 4b x 4f as 4b x 2 f-pairs: 8 FFMA2 per k (= 16 FMA).
// ---------------------------------------------------------------------------
#define GF 64   // features per block tile
#define GB 64   // batch per block tile
#define GK 32   // k per smem tile
#define SPLD 68 // padded sp row

__global__ void __launch_bounds__(256) gemm_part(const float* __restrict__ W1) {
    __shared__ __align__(16) float sp[GK][SPLD];    // pooled^T tile: [k][b]
    __shared__ __align__(16) float sw[GK][GF];      // W1 tile:       [k][f]

    const int fbase = blockIdx.x * GF;
    const int bbase = blockIdx.y * GB;
    const int k0    = blockIdx.z * KPS;
    const int t  = threadIdx.x;
    const int tx = t & 15;            // f group
    const int ty = t >> 4;            // b group

    unsigned long long acc2[4][2];    // [bi][f-pair]
    const unsigned long long zero2 = pack2(0.f, 0.f);
    #pragma unroll
    for (int i = 0; i < 4; i++) { acc2[i][0] = zero2; acc2[i][1] = zero2; }

    for (int kt = 0; kt < KPS; kt += GK) {
        #pragma unroll
        for (int i = t; i < GB * GK; i += 256) {
            int bb = i >> 5, kk = i & 31;
            sp[kk][bb] = g_pooled[(bbase + bb) * H + k0 + kt + kk];
        }
        #pragma unroll
        for (int i = t; i < GK * GF; i += 256) {
            int kk = i >> 6, ff = i & 63;
            sw[kk][ff] = W1[(size_t)(k0 + kt + kk) * H2 + fbase + ff];
        }
        __syncthreads();

        #pragma unroll
        for (int kk = 0; kk < GK; kk++) {
            float4 wv = *reinterpret_cast<const float4*>(&sw[kk][tx * 4]);
            float4 pv = *reinterpret_cast<const float4*>(&sp[kk][ty * 4]);
            unsigned long long w0 = pack2(wv.x, wv.y);
            unsigned long long w1 = pack2(wv.z, wv.w);
            unsigned long long p0 = pack2(pv.x, pv.x);
            unsigned long long p1 = pack2(pv.y, pv.y);
            unsigned long long p2 = pack2(pv.z, pv.z);
            unsigned long long p3 = pack2(pv.w, pv.w);
            acc2[0][0] = fma2(p0, w0, acc2[0][0]);
            acc2[0][1] = fma2(p0, w1, acc2[0][1]);
            acc2[1][0] = fma2(p1, w0, acc2[1][0]);
            acc2[1][1] = fma2(p1, w1, acc2[1][1]);
            acc2[2][0] = fma2(p2, w0, acc2[2][0]);
            acc2[2][1] = fma2(p2, w1, acc2[2][1]);
            acc2[3][0] = fma2(p3, w0, acc2[3][0]);
            acc2[3][1] = fma2(p3, w1, acc2[3][1]);
        }
        __syncthreads();
    }

    float* dst = g_hp + (size_t)blockIdx.z * (B * H2);
    #pragma unroll
    for (int bi = 0; bi < 4; bi++) {
        int row = bbase + ty * 4 + bi;
        float4 o;
        unpack2(acc2[bi][0], o.x, o.y);
        unpack2(acc2[bi][1], o.z, o.w);
        *reinterpret_cast<float4*>(dst + (size_t)row * H2 + fbase + tx * 4) = o;
    }
}

// ---------------------------------------------------------------------------
// Kernel 3: fused (k-partial fold + bias + exact GELU) -> LayerNorm -> head
// -> one-hot logits.  grid = B, block = 384 (one float4 of H2 per thread).
// Output layout: d_out[0..B) = pred; d_out[B..B+B*16) = logits.
// ---------------------------------------------------------------------------
__global__ void __launch_bounds__(384) ln_head(const float* __restrict__ b1,
                                               const float* __restrict__ gamma,
                                               const float* __restrict__ beta,
                                               const float* __restrict__ W2,
                                               const float* __restrict__ b2,
                                               float* __restrict__ out) {
    const int b = blockIdx.x;
    const int t = threadIdx.x;          // 0..383
    const int w = t >> 5, l = t & 31;   // 12 warps

    const size_t off = (size_t)b * H2 + t * 4;
    float4 pa = *reinterpret_cast<const float4*>(g_hp + off);
    float4 pc = *reinterpret_cast<const float4*>(g_hp + (size_t)B * H2 + off);
    float4 pd = *reinterpret_cast<const float4*>(g_hp + 2 * (size_t)B * H2 + off);
    float4 bb = *reinterpret_cast<const float4*>(b1 + t * 4);

    // fold k-splits + bias, exact GELU (matches approximate=False)
    const float r2 = 0.70710678118654752f;
    float h0 = pa.x + pc.x + pd.x + bb.x;
    float h1 = pa.y + pc.y + pd.y + bb.y;
    float h2 = pa.z + pc.z + pd.z + bb.z;
    float h3 = pa.w + pc.w + pd.w + bb.w;
    float4 x;
    x.x = 0.5f * h0 * (1.0f + erff(h0 * r2));
    x.y = 0.5f * h1 * (1.0f + erff(h1 * r2));
    x.z = 0.5f * h2 * (1.0f + erff(h2 * r2));
    x.w = 0.5f * h3 * (1.0f + erff(h3 * r2));

    float s  = (x.x + x.y) + (x.z + x.w);
    float sq = (x.x * x.x + x.y * x.y) + (x.z * x.z + x.w * x.w);

    __shared__ float sA[12], sB[12];
    #pragma unroll
    for (int o = 16; o; o >>= 1) {
        s  += __shfl_xor_sync(0xFFFFFFFFu, s,  o);
        sq += __shfl_xor_sync(0xFFFFFFFFu, sq, o);
    }
    if (l == 0) { sA[w] = s; sB[w] = sq; }
    __syncthreads();
    if (t < 32) {
        float a  = (l < 12) ? sA[l] : 0.f;
        float bq = (l < 12) ? sB[l] : 0.f;
        #pragma unroll
        for (int o = 8; o; o >>= 1) {
            a  += __shfl_xor_sync(0xFFFFFFFFu, a,  o);
            bq += __shfl_xor_sync(0xFFFFFFFFu, bq, o);
        }
        if (l == 0) { sA[0] = a; sB[0] = bq; }
    }
    __syncthreads();

    const float mu  = sA[0] * (1.0f / (float)H2);
    const float var = sB[0] * (1.0f / (float)H2) - mu * mu;
    const float rstd = rsqrtf(var + LN_EPS);

    __syncthreads();   // protect sA/sB reuse below

    float4 gm = *reinterpret_cast<const float4*>(gamma + t * 4);
    float4 bt = *reinterpret_cast<const float4*>(beta  + t * 4);
    float4 w2 = *reinterpret_cast<const float4*>(W2    + t * 4);

    float y0 = (x.x - mu) * rstd * gm.x + bt.x;
    float y1 = (x.y - mu) * rstd * gm.y + bt.y;
    float y2 = (x.z - mu) * rstd * gm.z + bt.z;
    float y3 = (x.w - mu) * rstd * gm.w + bt.w;

    float local = (y0 * w2.x + y1 * w2.y) + (y2 * w2.z + y3 * w2.w);
    #pragma unroll
    for (int o = 16; o; o >>= 1)
        local += __shfl_xor_sync(0xFFFFFFFFu, local, o);
    if (l == 0) sA[w] = local;
    __syncthreads();
    if (t < 32) {
        float a = (l < 12) ? sA[l] : 0.f;
        #pragma unroll
        for (int o = 8; o; o >>= 1)
            a += __shfl_xor_sync(0xFFFFFFFFu, a, o);
        if (l == 0) sA[0] = a;
    }
    __syncthreads();

    const float pred = sA[0] + b2[0];

    if (t == 0) out[b] = pred;

    // one-hot logits: round-half-even matches jnp.round; clamp [0,15]
    if (t < 16) {
        float r = rintf(pred);
        r = fminf(fmaxf(r, 0.f), 15.f);
        int aid = (int)r;
        out[B + b * 16 + t] = (t == aid) ? 1.0f : 0.0f;
    }
}

// ---------------------------------------------------------------------------
extern "C" void kernel_launch(void* const* d_in, const int* in_sizes, int n_in,
                              void* d_out, int out_size) {
    const float* v_emb = (const float*)d_in[0];  // [B,N,H]
    const float* W1    = (const float*)d_in[1];  // [H,2H]
    const float* b1    = (const float*)d_in[2];  // [2H]
    const float* gamma = (const float*)d_in[3];  // [2H]
    const float* beta  = (const float*)d_in[4];  // [2H]
    const float* W2    = (const float*)d_in[5];  // [2H,1]
    const float* b2    = (const float*)d_in[6];  // [1]
    float* out = (float*)d_out;

    pool_fused<<<dim3(S, B), 192>>>(v_emb);
    gemm_part<<<dim3(H2 / GF, B / GB, KS), 256>>>(W1);
    ln_head<<<B, 384>>>(b1, gamma, beta, W2, b2, out);
}

// round 16
// speedup vs baseline: 1.0104x; 1.0104x over previous
#include <cuda_runtime.h>
#include <math.h>

// Problem dims (fixed by reference)
#define B   128
#define N   2048
#define H   768
#define H2  1536
#define S   8           // N-splits for pooling (1024 blocks = one resident wave)
#define NPS (N / S)     // 256 rows per split
#define KS  3           // k-splits for gemm
#define KPS (H / KS)    // 256 k per split
#define NBLK (S * B)    // 1024 pool blocks (all resident: 148*7=1036)
#define LN_EPS 1e-5f

// Scratch (static device globals; no allocation allowed)
__device__ float g_partial[B * S * H];     // 3.1 MB
__device__ float g_pooled[B * H];          // 393 KB
__device__ float g_hp[KS * B * H2];        // 2.4 MB gemm k-split partials

// grid-barrier state (epoch-based; persists across graph replays)
__device__ unsigned g_bar_count = 0u;
__device__ unsigned g_bar_gen   = 0u;

// ---- packed f32x2 helpers (FFMA2: PTX-only, 2x fp32 FMA throughput) ----
__device__ __forceinline__ unsigned long long pack2(float lo, float hi) {
    unsigned long long r;
    asm("mov.b64 %0, {%1, %2};" : "=l"(r) : "f"(lo), "f"(hi));
    return r;
}
__device__ __forceinline__ unsigned long long fma2(
    unsigned long long a, unsigned long long b, unsigned long long c) {
    unsigned long long d;
    asm("fma.rn.f32x2 %0, %1, %2, %3;" : "=l"(d) : "l"(a), "l"(b), "l"(c));
    return d;
}
__device__ __forceinline__ void unpack2(unsigned long long v, float& lo, float& hi) {
    asm("mov.b64 {%0, %1}, %2;" : "=f"(lo), "=f"(hi) : "l"(v));
}

// ---------------------------------------------------------------------------
// Kernel 1: fused mean-pool (partial + fold). grid = (S=8, B) = 1024 blocks,
// 192 threads, __launch_bounds__(192,7) -> all resident.
// Proven R8/R15: 119-121us, 83-85% of HBM spec. DO NOT TOUCH.
// ---------------------------------------------------------------------------
__global__ void __launch_bounds__(192, 7) pool_fused(const float* __restrict__ v) {
    const int s = blockIdx.x;
    const int b = blockIdx.y;
    const int t = threadIdx.x;              // 0..191, 192*4 = 768 = H

    unsigned base_gen = 0;
    if (t == 0) base_gen = *(volatile unsigned*)&g_bar_gen;

    const float4* p = reinterpret_cast<const float4*>(
        v + ((size_t)b * N + (size_t)s * NPS) * H) + t;
    const int stride = H / 4;

    float4 a0 = make_float4(0.f,0.f,0.f,0.f), a1 = a0, a2 = a0, a3 = a0;
    #pragma unroll 1
    for (int n = 0; n < NPS; n += 4) {
        float4 x0 = __ldcs(p + (n + 0) * stride);
        float4 x1 = __ldcs(p + (n + 1) * stride);
        float4 x2 = __ldcs(p + (n + 2) * stride);
        float4 x3 = __ldcs(p + (n + 3) * stride);
        a0.x += x0.x; a0.y += x0.y; a0.z += x0.z; a0.w += x0.w;
        a1.x += x1.x; a1.y += x1.y; a1.z += x1.z; a1.w += x1.w;
        a2.x += x2.x; a2.y += x2.y; a2.z += x2.z; a2.w += x2.w;
        a3.x += x3.x; a3.y += x3.y; a3.z += x3.z; a3.w += x3.w;
    }
    float4 acc;
    acc.x = (a0.x + a1.x) + (a2.x + a3.x);
    acc.y = (a0.y + a1.y) + (a2.y + a3.y);
    acc.z = (a0.z + a1.z) + (a2.z + a3.z);
    acc.w = (a0.w + a1.w) + (a2.w + a3.w);
    *(reinterpret_cast<float4*>(g_partial + ((size_t)b * S + s) * H) + t) = acc;

    // grid barrier (all 1024 blocks resident by construction)
    __syncthreads();
    if (t == 0) {
        const unsigned target = base_gen + 1u;
        __threadfence();
        if (atomicAdd(&g_bar_count, 1u) == (unsigned)(NBLK - 1)) {
            g_bar_count = 0u;
            __threadfence();
            *(volatile unsigned*)&g_bar_gen = target;
        } else if (s == 0) {
            while ((int)(*(volatile unsigned*)&g_bar_gen - target) < 0)
                __nanosleep(64);
        }
        __threadfence();
    }
    __syncthreads();

    // fold S partials, scale by 1/N (128 blocks participate)
    if (s == 0) {
        float4 r = make_float4(0.f, 0.f, 0.f, 0.f);
        #pragma unroll
        for (int ss = 0; ss < S; ss++) {
            float4 x = *(reinterpret_cast<const float4*>(
                g_partial + ((size_t)b * S + ss) * H) + t);
            r.x += x.x; r.y += x.y; r.z += x.z; r.w += x.w;
        }
        const float inv = 1.0f / (float)N;
        r.x *= inv; r.y *= inv; r.z *= inv; r.w *= inv;
        *(reinterpret_cast<float4*>(g_pooled + (size_t)b * H) + t) = r;
    }
}

// ---------------------------------------------------------------------------
// Kernel 2: k-split GEMM partials, FFMA2 inner loop. Launched with PDL:
// its setup/scheduling overlaps pool_fused; cudaGridDependencySynchronize()
// gates the first read of g_pooled.
// grid = (24, 2, 3) = 144 blocks, 256 threads, thread tile 4b x 2 f-pairs.
// ---------------------------------------------------------------------------
#define GF 64   // features per block tile
#define GB 64   // batch per block tile
#define GK 32   // k per smem tile
#define SPLD 68 // padded sp row

__global__ void __launch_bounds__(256) gemm_part(const float* __restrict__ W1) {
    __shared__ __align__(16) float sp[GK][SPLD];    // pooled^T tile: [k][b]
    __shared__ __align__(16) float sw[GK][GF];      // W1 tile:       [k][f]

    const int fbase = blockIdx.x * GF;
    const int bbase = blockIdx.y * GB;
    const int k0    = blockIdx.z * KPS;
    const int t  = threadIdx.x;
    const int tx = t & 15;            // f group
    const int ty = t >> 4;            // b group

    unsigned long long acc2[4][2];    // [bi][f-pair]
    const unsigned long long zero2 = pack2(0.f, 0.f);
    #pragma unroll
    for (int i = 0; i < 4; i++) { acc2[i][0] = zero2; acc2[i][1] = zero2; }

    // wait for pool_fused's writes to g_pooled to be visible
    cudaGridDependencySynchronize();

    for (int kt = 0; kt < KPS; kt += GK) {
        #pragma unroll
        for (int i = t; i < GB * GK; i += 256) {
            int bb = i >> 5, kk = i & 31;
            sp[kk][bb] = g_pooled[(bbase + bb) * H + k0 + kt + kk];
        }
        #pragma unroll
        for (int i = t; i < GK * GF; i += 256) {
            int kk = i >> 6, ff = i & 63;
            sw[kk][ff] = W1[(size_t)(k0 + kt + kk) * H2 + fbase + ff];
        }
        __syncthreads();

        #pragma unroll
        for (int kk = 0; kk < GK; kk++) {
            float4 wv = *reinterpret_cast<const float4*>(&sw[kk][tx * 4]);
            float4 pv = *reinterpret_cast<const float4*>(&sp[kk][ty * 4]);
            unsigned long long w0 = pack2(wv.x, wv.y);
            unsigned long long w1 = pack2(wv.z, wv.w);
            unsigned long long p0 = pack2(pv.x, pv.x);
            unsigned long long p1 = pack2(pv.y, pv.y);
            unsigned long long p2 = pack2(pv.z, pv.z);
            unsigned long long p3 = pack2(pv.w, pv.w);
            acc2[0][0] = fma2(p0, w0, acc2[0][0]);
            acc2[0][1] = fma2(p0, w1, acc2[0][1]);
            acc2[1][0] = fma2(p1, w0, acc2[1][0]);
            acc2[1][1] = fma2(p1, w1, acc2[1][1]);
            acc2[2][0] = fma2(p2, w0, acc2[2][0]);
            acc2[2][1] = fma2(p2, w1, acc2[2][1]);
            acc2[3][0] = fma2(p3, w0, acc2[3][0]);
            acc2[3][1] = fma2(p3, w1, acc2[3][1]);
        }
        __syncthreads();
    }

    float* dst = g_hp + (size_t)blockIdx.z * (B * H2);
    #pragma unroll
    for (int bi = 0; bi < 4; bi++) {
        int row = bbase + ty * 4 + bi;
        float4 o;
        unpack2(acc2[bi][0], o.x, o.y);
        unpack2(acc2[bi][1], o.z, o.w);
        *reinterpret_cast<float4*>(dst + (size_t)row * H2 + fbase + tx * 4) = o;
    }
}

// ---------------------------------------------------------------------------
// Kernel 3: fused (k-partial fold + bias + exact GELU) -> LayerNorm -> head
// -> one-hot logits. PDL on gemm_part: preloads all non-dependent inputs
// (b1/gamma/beta/W2/b2) BEFORE the dependency sync, then reads g_hp.
// grid = B, block = 384.  d_out[0..B)=pred; d_out[B..B+B*16)=logits.
// ---------------------------------------------------------------------------
__global__ void __launch_bounds__(384) ln_head(const float* __restrict__ b1,
                                               const float* __restrict__ gamma,
                                               const float* __restrict__ beta,
                                               const float* __restrict__ W2,
                                               const float* __restrict__ b2,
                                               float* __restrict__ out) {
    const int b = blockIdx.x;
    const int t = threadIdx.x;          // 0..383
    const int w = t >> 5, l = t & 31;   // 12 warps

    // prologue: loads independent of gemm_part output (overlap its execution)
    float4 bb = *reinterpret_cast<const float4*>(b1    + t * 4);
    float4 gm = *reinterpret_cast<const float4*>(gamma + t * 4);
    float4 bt = *reinterpret_cast<const float4*>(beta  + t * 4);
    float4 w2 = *reinterpret_cast<const float4*>(W2    + t * 4);
    const float b2v = b2[0];

    // wait for gemm_part's writes to g_hp
    cudaGridDependencySynchronize();

    const size_t off = (size_t)b * H2 + t * 4;
    float4 pa = *reinterpret_cast<const float4*>(g_hp + off);
    float4 pc = *reinterpret_cast<const float4*>(g_hp + (size_t)B * H2 + off);
    float4 pd = *reinterpret_cast<const float4*>(g_hp + 2 * (size_t)B * H2 + off);

    // fold k-splits + bias, exact GELU (matches approximate=False)
    const float r2 = 0.70710678118654752f;
    float h0 = pa.x + pc.x + pd.x + bb.x;
    float h1 = pa.y + pc.y + pd.y + bb.y;
    float h2 = pa.z + pc.z + pd.z + bb.z;
    float h3 = pa.w + pc.w + pd.w + bb.w;
    float4 x;
    x.x = 0.5f * h0 * (1.0f + erff(h0 * r2));
    x.y = 0.5f * h1 * (1.0f + erff(h1 * r2));
    x.z = 0.5f * h2 * (1.0f + erff(h2 * r2));
    x.w = 0.5f * h3 * (1.0f + erff(h3 * r2));

    float s  = (x.x + x.y) + (x.z + x.w);
    float sq = (x.x * x.x + x.y * x.y) + (x.z * x.z + x.w * x.w);

    __shared__ float sA[12], sB[12];
    #pragma unroll
    for (int o = 16; o; o >>= 1) {
        s  += __shfl_xor_sync(0xFFFFFFFFu, s,  o);
        sq += __shfl_xor_sync(0xFFFFFFFFu, sq, o);
    }
    if (l == 0) { sA[w] = s; sB[w] = sq; }
    __syncthreads();
    if (t < 32) {
        float a  = (l < 12) ? sA[l] : 0.f;
        float bq = (l < 12) ? sB[l] : 0.f;
        #pragma unroll
        for (int o = 8; o; o >>= 1) {
            a  += __shfl_xor_sync(0xFFFFFFFFu, a,  o);
            bq += __shfl_xor_sync(0xFFFFFFFFu, bq, o);
        }
        if (l == 0) { sA[0] = a; sB[0] = bq; }
    }
    __syncthreads();

    const float mu  = sA[0] * (1.0f / (float)H2);
    const float var = sB[0] * (1.0f / (float)H2) - mu * mu;
    const float rstd = rsqrtf(var + LN_EPS);

    __syncthreads();   // protect sA/sB reuse below

    float y0 = (x.x - mu) * rstd * gm.x + bt.x;
    float y1 = (x.y - mu) * rstd * gm.y + bt.y;
    float y2 = (x.z - mu) * rstd * gm.z + bt.z;
    float y3 = (x.w - mu) * rstd * gm.w + bt.w;

    float local = (y0 * w2.x + y1 * w2.y) + (y2 * w2.z + y3 * w2.w);
    #pragma unroll
    for (int o = 16; o; o >>= 1)
        local += __shfl_xor_sync(0xFFFFFFFFu, local, o);
    if (l == 0) sA[w] = local;
    __syncthreads();
    if (t < 32) {
        float a = (l < 12) ? sA[l] : 0.f;
        #pragma unroll
        for (int o = 8; o; o >>= 1)
            a += __shfl_xor_sync(0xFFFFFFFFu, a, o);
        if (l == 0) sA[0] = a;
    }
    __syncthreads();

    const float pred = sA[0] + b2v;

    if (t == 0) out[b] = pred;

    // one-hot logits: round-half-even matches jnp.round; clamp [0,15]
    if (t < 16) {
        float r = rintf(pred);
        r = fminf(fmaxf(r, 0.f), 15.f);
        int aid = (int)r;
        out[B + b * 16 + t] = (t == aid) ? 1.0f : 0.0f;
    }
}

// ---------------------------------------------------------------------------
extern "C" void kernel_launch(void* const* d_in, const int* in_sizes, int n_in,
                              void* d_out, int out_size) {
    const float* v_emb = (const float*)d_in[0];  // [B,N,H]
    const float* W1    = (const float*)d_in[1];  // [H,2H]
    const float* b1    = (const float*)d_in[2];  // [2H]
    const float* gamma = (const float*)d_in[3];  // [2H]
    const float* beta  = (const float*)d_in[4];  // [2H]
    const float* W2    = (const float*)d_in[5];  // [2H,1]
    const float* b2    = (const float*)d_in[6];  // [1]
    float* out = (float*)d_out;

    pool_fused<<<dim3(S, B), 192>>>(v_emb);

    // PDL launches: setup overlaps the predecessor; data dependence enforced
    // by cudaGridDependencySynchronize() inside each kernel.
    cudaLaunchAttribute pdl_attr;
    pdl_attr.id = cudaLaunchAttributeProgrammaticStreamSerialization;
    pdl_attr.val.programmaticStreamSerializationAllowed = 1;

    {
        cudaLaunchConfig_t cfg = {};
        cfg.gridDim  = dim3(H2 / GF, B / GB, KS);
        cfg.blockDim = dim3(256);
        cfg.attrs    = &pdl_attr;
        cfg.numAttrs = 1;
        cudaLaunchKernelEx(&cfg, gemm_part, W1);
    }
    {
        cudaLaunchConfig_t cfg = {};
        cfg.gridDim  = dim3(B);
        cfg.blockDim = dim3(384);
        cfg.attrs    = &pdl_attr;
        cfg.numAttrs = 1;
        cudaLaunchKernelEx(&cfg, ln_head, b1, gamma, beta, W2, b2, out);
    }
}

// round 17
// speedup vs baseline: 1.0120x; 1.0017x over previous
#include <cuda_runtime.h>
#include <math.h>

// Problem dims (fixed by reference)
#define B   128
#define N   2048
#define H   768
#define H2  1536
#define S   8           // N-splits for pooling (1024 blocks = one resident wave)
#define NPS (N / S)     // 256 rows per split
#define KS  3           // k-splits for gemm
#define KPS (H / KS)    // 256 k per split
#define NBLK (S * B)    // 1024 pool blocks (all resident: 148*7=1036)
#define LN_EPS 1e-5f

// Scratch (static device globals; no allocation allowed)
__device__ float g_partial[B * S * H];     // 3.1 MB
__device__ float g_pooled[B * H];          // 393 KB
__device__ float g_hp[KS * B * H2];        // 2.4 MB gemm k-split partials

// grid-barrier state (epoch-based; persists across graph replays)
__device__ unsigned g_bar_count = 0u;
__device__ unsigned g_bar_gen   = 0u;

// ---- packed f32x2 helpers (FFMA2: PTX-only, 2x fp32 FMA throughput) ----
__device__ __forceinline__ unsigned long long pack2(float lo, float hi) {
    unsigned long long r;
    asm("mov.b64 %0, {%1, %2};" : "=l"(r) : "f"(lo), "f"(hi));
    return r;
}
__device__ __forceinline__ unsigned long long fma2(
    unsigned long long a, unsigned long long b, unsigned long long c) {
    unsigned long long d;
    asm("fma.rn.f32x2 %0, %1, %2, %3;" : "=l"(d) : "l"(a), "l"(b), "l"(c));
    return d;
}
__device__ __forceinline__ void unpack2(unsigned long long v, float& lo, float& hi) {
    asm("mov.b64 {%0, %1}, %2;" : "=f"(lo), "=f"(hi) : "l"(v));
}

// ---------------------------------------------------------------------------
// Kernel 1: fused mean-pool (partial + fold). grid = (S=8, B) = 1024 blocks,
// 192 threads, __launch_bounds__(192,7) -> all resident.
// Proven R8/R15/R16: 119-121us, 83-85% of HBM spec. Arithmetic untouched.
// NEW: early PDL trigger -> dependents release at FOLD COMPLETION, not at
// kernel teardown (1024-block drain + L1 flush hidden).
// ---------------------------------------------------------------------------
__global__ void __launch_bounds__(192, 7) pool_fused(const float* __restrict__ v) {
    const int s = blockIdx.x;
    const int b = blockIdx.y;
    const int t = threadIdx.x;              // 0..191, 192*4 = 768 = H

    unsigned base_gen = 0;
    if (t == 0) base_gen = *(volatile unsigned*)&g_bar_gen;

    const float4* p = reinterpret_cast<const float4*>(
        v + ((size_t)b * N + (size_t)s * NPS) * H) + t;
    const int stride = H / 4;

    float4 a0 = make_float4(0.f,0.f,0.f,0.f), a1 = a0, a2 = a0, a3 = a0;
    #pragma unroll 1
    for (int n = 0; n < NPS; n += 4) {
        float4 x0 = __ldcs(p + (n + 0) * stride);
        float4 x1 = __ldcs(p + (n + 1) * stride);
        float4 x2 = __ldcs(p + (n + 2) * stride);
        float4 x3 = __ldcs(p + (n + 3) * stride);
        a0.x += x0.x; a0.y += x0.y; a0.z += x0.z; a0.w += x0.w;
        a1.x += x1.x; a1.y += x1.y; a1.z += x1.z; a1.w += x1.w;
        a2.x += x2.x; a2.y += x2.y; a2.z += x2.z; a2.w += x2.w;
        a3.x += x3.x; a3.y += x3.y; a3.z += x3.z; a3.w += x3.w;
    }
    float4 acc;
    acc.x = (a0.x + a1.x) + (a2.x + a3.x);
    acc.y = (a0.y + a1.y) + (a2.y + a3.y);
    acc.z = (a0.z + a1.z) + (a2.z + a3.z);
    acc.w = (a0.w + a1.w) + (a2.w + a3.w);
    *(reinterpret_cast<float4*>(g_partial + ((size_t)b * S + s) * H) + t) = acc;

    // grid barrier (all 1024 blocks resident by construction)
    __syncthreads();
    if (t == 0) {
        const unsigned target = base_gen + 1u;
        __threadfence();
        if (atomicAdd(&g_bar_count, 1u) == (unsigned)(NBLK - 1)) {
            g_bar_count = 0u;
            __threadfence();
            *(volatile unsigned*)&g_bar_gen = target;
        } else if (s == 0) {
            while ((int)(*(volatile unsigned*)&g_bar_gen - target) < 0)
                __nanosleep(64);
        }
        __threadfence();
    }
    __syncthreads();

    // fold S partials, scale by 1/N (128 blocks participate)
    if (s == 0) {
        float4 r = make_float4(0.f, 0.f, 0.f, 0.f);
        #pragma unroll
        for (int ss = 0; ss < S; ss++) {
            float4 x = *(reinterpret_cast<const float4*>(
                g_partial + ((size_t)b * S + ss) * H) + t);
            r.x += x.x; r.y += x.y; r.z += x.z; r.w += x.w;
        }
        const float inv = 1.0f / (float)N;
        r.x *= inv; r.y *= inv; r.z *= inv; r.w *= inv;
        *(reinterpret_cast<float4*>(g_pooled + (size_t)b * H) + t) = r;
        __threadfence();   // make g_pooled visible before trigger
    }
    // Every block triggers once: non-fold blocks immediately after the
    // barrier, fold blocks after their g_pooled store. The "all triggered"
    // point == fold completion -> dependents release right then.
    cudaTriggerProgrammaticLaunchCompletion();
}

// ---------------------------------------------------------------------------
// Kernel 2: k-split GEMM partials, FFMA2 inner loop. PDL secondary:
// pre-sync preamble loads W1 tile 0 + L2-prefetches the whole W1 slice
// (g_pooled-independent), then waits, then runs the mainloop.
// grid = (24, 2, 3) = 144 blocks, 256 threads, thread tile 4b x 2 f-pairs.
// ---------------------------------------------------------------------------
#define GF 64   // features per block tile
#define GB 64   // batch per block tile
#define GK 32   // k per smem tile
#define SPLD 68 // padded sp row

__global__ void __launch_bounds__(256) gemm_part(const float* __restrict__ W1) {
    __shared__ __align__(16) float sp[GK][SPLD];    // pooled^T tile: [k][b]
    __shared__ __align__(16) float sw[GK][GF];      // W1 tile:       [k][f]

    const int fbase = blockIdx.x * GF;
    const int bbase = blockIdx.y * GB;
    const int k0    = blockIdx.z * KPS;
    const int t  = threadIdx.x;
    const int tx = t & 15;            // f group
    const int ty = t >> 4;            // b group

    unsigned long long acc2[4][2];    // [bi][f-pair]
    const unsigned long long zero2 = pack2(0.f, 0.f);
    #pragma unroll
    for (int i = 0; i < 4; i++) { acc2[i][0] = zero2; acc2[i][1] = zero2; }

    // ---- pre-sync preamble: W1-only work (independent of g_pooled) ----
    // load sw tile for kt=0
    #pragma unroll
    for (int i = t; i < GK * GF; i += 256) {
        int kk = i >> 6, ff = i & 63;
        sw[kk][ff] = W1[(size_t)(k0 + kk) * H2 + fbase + ff];
    }
    // L2-prefetch the rest of this block's W1 slice (KPS x GF floats)
    for (int kk = GK + (t >> 3); kk < KPS; kk += 32) {
        const float* ptr = W1 + (size_t)(k0 + kk) * H2 + fbase + (t & 7) * 8;
        asm volatile("prefetch.global.L2 [%0];" :: "l"(ptr));
    }
    __syncthreads();   // sw tile 0 complete

    // wait for pool_fused's g_pooled (released at fold completion via trigger)
    cudaGridDependencySynchronize();

    for (int kt = 0; kt < KPS; kt += GK) {
        #pragma unroll
        for (int i = t; i < GB * GK; i += 256) {
            int bb = i >> 5, kk = i & 31;
            sp[kk][bb] = g_pooled[(bbase + bb) * H + k0 + kt + kk];
        }
        if (kt != 0) {
            #pragma unroll
            for (int i = t; i < GK * GF; i += 256) {
                int kk = i >> 6, ff = i & 63;
                sw[kk][ff] = W1[(size_t)(k0 + kt + kk) * H2 + fbase + ff];
            }
        }
        __syncthreads();

        #pragma unroll
        for (int kk = 0; kk < GK; kk++) {
            float4 wv = *reinterpret_cast<const float4*>(&sw[kk][tx * 4]);
            float4 pv = *reinterpret_cast<const float4*>(&sp[kk][ty * 4]);
            unsigned long long w0 = pack2(wv.x, wv.y);
            unsigned long long w1 = pack2(wv.z, wv.w);
            unsigned long long p0 = pack2(pv.x, pv.x);
            unsigned long long p1 = pack2(pv.y, pv.y);
            unsigned long long p2 = pack2(pv.z, pv.z);
            unsigned long long p3 = pack2(pv.w, pv.w);
            acc2[0][0] = fma2(p0, w0, acc2[0][0]);
            acc2[0][1] = fma2(p0, w1, acc2[0][1]);
            acc2[1][0] = fma2(p1, w0, acc2[1][0]);
            acc2[1][1] = fma2(p1, w1, acc2[1][1]);
            acc2[2][0] = fma2(p2, w0, acc2[2][0]);
            acc2[2][1] = fma2(p2, w1, acc2[2][1]);
            acc2[3][0] = fma2(p3, w0, acc2[3][0]);
            acc2[3][1] = fma2(p3, w1, acc2[3][1]);
        }
        __syncthreads();
    }

    float* dst = g_hp + (size_t)blockIdx.z * (B * H2);
    #pragma unroll
    for (int bi = 0; bi < 4; bi++) {
        int row = bbase + ty * 4 + bi;
        float4 o;
        unpack2(acc2[bi][0], o.x, o.y);
        unpack2(acc2[bi][1], o.z, o.w);
        *reinterpret_cast<float4*>(dst + (size_t)row * H2 + fbase + tx * 4) = o;
    }

    __threadfence();   // g_hp visible before trigger
    cudaTriggerProgrammaticLaunchCompletion();   // release ln_head now
}

// ---------------------------------------------------------------------------
// Kernel 3: fused (k-partial fold + bias + exact GELU) -> LayerNorm -> head
// -> one-hot logits. PDL secondary of gemm_part: preloads all non-dependent
// inputs before the dependency sync, then reads g_hp.
// grid = B, block = 384.  d_out[0..B)=pred; d_out[B..B+B*16)=logits.
// ---------------------------------------------------------------------------
__global__ void __launch_bounds__(384) ln_head(const float* __restrict__ b1,
                                               const float* __restrict__ gamma,
                                               const float* __restrict__ beta,
                                               const float* __restrict__ W2,
                                               const float* __restrict__ b2,
                                               float* __restrict__ out) {
    const int b = blockIdx.x;
    const int t = threadIdx.x;          // 0..383
    const int w = t >> 5, l = t & 31;   // 12 warps

    // prologue: loads independent of gemm_part output (overlap its execution)
    float4 bb = *reinterpret_cast<const float4*>(b1    + t * 4);
    float4 gm = *reinterpret_cast<const float4*>(gamma + t * 4);
    float4 bt = *reinterpret_cast<const float4*>(beta  + t * 4);
    float4 w2 = *reinterpret_cast<const float4*>(W2    + t * 4);
    const float b2v = b2[0];

    // wait for gemm_part's writes to g_hp
    cudaGridDependencySynchronize();

    const size_t off = (size_t)b * H2 + t * 4;
    float4 pa = *reinterpret_cast<const float4*>(g_hp + off);
    float4 pc = *reinterpret_cast<const float4*>(g_hp + (size_t)B * H2 + off);
    float4 pd = *reinterpret_cast<const float4*>(g_hp + 2 * (size_t)B * H2 + off);

    // fold k-splits + bias, exact GELU (matches approximate=False)
    const float r2 = 0.70710678118654752f;
    float h0 = pa.x + pc.x + pd.x + bb.x;
    float h1 = pa.y + pc.y + pd.y + bb.y;
    float h2 = pa.z + pc.z + pd.z + bb.z;
    float h3 = pa.w + pc.w + pd.w + bb.w;
    float4 x;
    x.x = 0.5f * h0 * (1.0f + erff(h0 * r2));
    x.y = 0.5f * h1 * (1.0f + erff(h1 * r2));
    x.z = 0.5f * h2 * (1.0f + erff(h2 * r2));
    x.w = 0.5f * h3 * (1.0f + erff(h3 * r2));

    float s  = (x.x + x.y) + (x.z + x.w);
    float sq = (x.x * x.x + x.y * x.y) + (x.z * x.z + x.w * x.w);

    __shared__ float sA[12], sB[12];
    #pragma unroll
    for (int o = 16; o; o >>= 1) {
        s  += __shfl_xor_sync(0xFFFFFFFFu, s,  o);
        sq += __shfl_xor_sync(0xFFFFFFFFu, sq, o);
    }
    if (l == 0) { sA[w] = s; sB[w] = sq; }
    __syncthreads();
    if (t < 32) {
        float a  = (l < 12) ? sA[l] : 0.f;
        float bq = (l < 12) ? sB[l] : 0.f;
        #pragma unroll
        for (int o = 8; o; o >>= 1) {
            a  += __shfl_xor_sync(0xFFFFFFFFu, a,  o);
            bq += __shfl_xor_sync(0xFFFFFFFFu, bq, o);
        }
        if (l == 0) { sA[0] = a; sB[0] = bq; }
    }
    __syncthreads();

    const float mu  = sA[0] * (1.0f / (float)H2);
    const float var = sB[0] * (1.0f / (float)H2) - mu * mu;
    const float rstd = rsqrtf(var + LN_EPS);

    __syncthreads();   // protect sA/sB reuse below

    float y0 = (x.x - mu) * rstd * gm.x + bt.x;
    float y1 = (x.y - mu) * rstd * gm.y + bt.y;
    float y2 = (x.z - mu) * rstd * gm.z + bt.z;
    float y3 = (x.w - mu) * rstd * gm.w + bt.w;

    float local = (y0 * w2.x + y1 * w2.y) + (y2 * w2.z + y3 * w2.w);
    #pragma unroll
    for (int o = 16; o; o >>= 1)
        local += __shfl_xor_sync(0xFFFFFFFFu, local, o);
    if (l == 0) sA[w] = local;
    __syncthreads();
    if (t < 32) {
        float a = (l < 12) ? sA[l] : 0.f;
        #pragma unroll
        for (int o = 8; o; o >>= 1)
            a += __shfl_xor_sync(0xFFFFFFFFu, a, o);
        if (l == 0) sA[0] = a;
    }
    __syncthreads();

    const float pred = sA[0] + b2v;

    if (t == 0) out[b] = pred;

    // one-hot logits: round-half-even matches jnp.round; clamp [0,15]
    if (t < 16) {
        float r = rintf(pred);
        r = fminf(fmaxf(r, 0.f), 15.f);
        int aid = (int)r;
        out[B + b * 16 + t] = (t == aid) ? 1.0f : 0.0f;
    }
}

// ---------------------------------------------------------------------------
extern "C" void kernel_launch(void* const* d_in, const int* in_sizes, int n_in,
                              void* d_out, int out_size) {
    const float* v_emb = (const float*)d_in[0];  // [B,N,H]
    const float* W1    = (const float*)d_in[1];  // [H,2H]
    const float* b1    = (const float*)d_in[2];  // [2H]
    const float* gamma = (const float*)d_in[3];  // [2H]
    const float* beta  = (const float*)d_in[4];  // [2H]
    const float* W2    = (const float*)d_in[5];  // [2H,1]
    const float* b2    = (const float*)d_in[6];  // [1]
    float* out = (float*)d_out;

    pool_fused<<<dim3(S, B), 192>>>(v_emb);

    // PDL launches: setup overlaps the predecessor; data dependence enforced
    // by cudaGridDependencySynchronize() inside each kernel, released early
    // by the producers' cudaTriggerProgrammaticLaunchCompletion().
    cudaLaunchAttribute pdl_attr;
    pdl_attr.id = cudaLaunchAttributeProgrammaticStreamSerialization;
    pdl_attr.val.programmaticStreamSerializationAllowed = 1;

    {
        cudaLaunchConfig_t cfg = {};
        cfg.gridDim  = dim3(H2 / GF, B / GB, KS);
        cfg.blockDim = dim3(256);
        cfg.attrs    = &pdl_attr;
        cfg.numAttrs = 1;
        cudaLaunchKernelEx(&cfg, gemm_part, W1);
    }
    {
        cudaLaunchConfig_t cfg = {};
        cfg.gridDim  = dim3(B);
        cfg.blockDim = dim3(384);
        cfg.attrs    = &pdl_attr;
        cfg.numAttrs = 1;
        cudaLaunchKernelEx(&cfg, ln_head, b1, gamma, beta, W2, b2, out);
    }
}